// round 2
// baseline (speedup 1.0000x reference)
#include <cuda_runtime.h>

// x is [8, 4, 1048576] fp32.
constexpr int T_IN  = 1048576;
constexpr int T_OUT = T_IN - 12;        // 1048564
constexpr int NVEC  = T_OUT / 4;        // 262141 float4 outputs per row
constexpr int ROWS  = 8 * 4;            // 32 rows
constexpr int VPT   = 4;                // float4 vectors per thread (16 outputs)
constexpr int TPR   = (NVEC + VPT - 1) / VPT;   // 65536 threads per row
constexpr int TPB   = 256;
constexpr int BPR   = TPR / TPB;        // 256 blocks per row (exact)

// Composite 13-tap kernel (fd conv gauss), computed on device at runtime.
__device__ float g_comp[16];

__global__ void compute_comp_kernel(const float* __restrict__ fd,
                                    const float* __restrict__ gauss) {
    int k = threadIdx.x;
    if (k < 13) {
        float s = 0.0f;
        #pragma unroll
        for (int i = 0; i < 5; i++) {
            int j = k - i;
            if (j >= 0 && j < 9) s += fd[i] * gauss[j];
        }
        g_comp[k] = s;
    }
}

__global__ __launch_bounds__(TPB)
void stencil13_kernel(const float* __restrict__ x, float* __restrict__ out) {
    int gid = blockIdx.x * TPB + threadIdx.x;   // thread index within row
    int row = blockIdx.y;

    float comp[13];
    #pragma unroll
    for (int k = 0; k < 13; k++) comp[k] = g_comp[k];

    const float* xrow = x + (long)row * T_IN;
    float*       orow = out + (long)row * T_OUT;

    long t0 = 16L * gid;                        // first output index for this thread

    if (gid < TPR - 1) {
        // Full path: 16 outputs, inputs x[t0 .. t0+27] (7 aligned float4 loads)
        const float4* xin = reinterpret_cast<const float4*>(xrow + t0);
        float xs[28];
        #pragma unroll
        for (int v = 0; v < 7; v++) {
            float4 f = xin[v];
            xs[4*v+0] = f.x; xs[4*v+1] = f.y; xs[4*v+2] = f.z; xs[4*v+3] = f.w;
        }

        float o[16];
        #pragma unroll
        for (int j = 0; j < 16; j++) o[j] = 0.0f;
        #pragma unroll
        for (int k = 0; k < 13; k++) {
            float ck = comp[k];
            #pragma unroll
            for (int j = 0; j < 16; j++) o[j] = fmaf(ck, xs[j + k], o[j]);
        }

        float4* ov = reinterpret_cast<float4*>(orow + t0);
        #pragma unroll
        for (int v = 0; v < 4; v++) {
            float4 f;
            f.x = o[4*v+0]; f.y = o[4*v+1]; f.z = o[4*v+2]; f.w = o[4*v+3];
            ov[v] = f;
        }
    } else {
        // Tail thread (one per row): NVEC = 4*65535 + 1, so exactly 1 vec left.
        // Inputs x[t0 .. t0+15], ending exactly at x[T_IN-1].
        const float4* xin = reinterpret_cast<const float4*>(xrow + t0);
        float xs[16];
        #pragma unroll
        for (int v = 0; v < 4; v++) {
            float4 f = xin[v];
            xs[4*v+0] = f.x; xs[4*v+1] = f.y; xs[4*v+2] = f.z; xs[4*v+3] = f.w;
        }
        float o0 = 0.f, o1 = 0.f, o2 = 0.f, o3 = 0.f;
        #pragma unroll
        for (int k = 0; k < 13; k++) {
            float ck = comp[k];
            o0 = fmaf(ck, xs[k + 0], o0);
            o1 = fmaf(ck, xs[k + 1], o1);
            o2 = fmaf(ck, xs[k + 2], o2);
            o3 = fmaf(ck, xs[k + 3], o3);
        }
        float4 f; f.x = o0; f.y = o1; f.z = o2; f.w = o3;
        *reinterpret_cast<float4*>(orow + t0) = f;
    }
}

extern "C" void kernel_launch(void* const* d_in, const int* in_sizes, int n_in,
                              void* d_out, int out_size) {
    const float* x     = (const float*)d_in[0];
    const float* fd    = (const float*)d_in[1];
    const float* gauss = (const float*)d_in[2];
    float* out = (float*)d_out;

    compute_comp_kernel<<<1, 32>>>(fd, gauss);

    dim3 grid(BPR, ROWS);
    stencil13_kernel<<<grid, TPB>>>(x, out);
}

// round 3
// speedup vs baseline: 1.1635x; 1.1635x over previous
#include <cuda_runtime.h>

// x is [8, 4, 1048576] fp32.
constexpr int T_IN  = 1048576;
constexpr int T_OUT = T_IN - 12;        // 1048564
constexpr int NVEC  = T_OUT / 4;        // 262141 float4 outputs per row
constexpr int ROWS  = 8 * 4;            // 32 rows
constexpr int TPB   = 256;
constexpr int KINT  = 2;                // interleaved vectors per thread
constexpr int VPB   = TPB * KINT;       // 512 output vectors per block
constexpr int BPR   = (NVEC + VPB - 1) / VPB;   // 512 blocks per row

// Composite 13-tap kernel (fd conv gauss), computed on device at runtime.
__device__ float g_comp[16];

__global__ void compute_comp_kernel(const float* __restrict__ fd,
                                    const float* __restrict__ gauss) {
    int k = threadIdx.x;
    if (k < 13) {
        float s = 0.0f;
        #pragma unroll
        for (int i = 0; i < 5; i++) {
            int j = k - i;
            if (j >= 0 && j < 9) s += fd[i] * gauss[j];
        }
        g_comp[k] = s;
    }
}

__global__ __launch_bounds__(TPB)
void stencil13_kernel(const float* __restrict__ x, float* __restrict__ out) {
    const int base = blockIdx.x * VPB;
    const int row  = blockIdx.y;

    const float* xrow = x + (long)row * T_IN;
    float*       orow = out + (long)row * T_OUT;

    const int v0 = base + threadIdx.x;          // always < NVEC (511*512+255 < NVEC)
    const int v1 = v0 + TPB;                    // needs guard (3 excess per row)
    const bool p1 = (v1 < NVEC);

    // Front-batch all loads: 8 independent LDG.128 (4 predicated).
    const float4* xin0 = reinterpret_cast<const float4*>(xrow + 4L * v0);
    const float4* xin1 = reinterpret_cast<const float4*>(xrow + 4L * v1);

    float4 a0 = xin0[0], a1 = xin0[1], a2 = xin0[2], a3 = xin0[3];
    float4 b0, b1, b2, b3;
    if (p1) { b0 = xin1[0]; b1 = xin1[1]; b2 = xin1[2]; b3 = xin1[3]; }

    float comp[13];
    #pragma unroll
    for (int k = 0; k < 13; k++) comp[k] = g_comp[k];

    float xs0[16] = { a0.x, a0.y, a0.z, a0.w,  a1.x, a1.y, a1.z, a1.w,
                      a2.x, a2.y, a2.z, a2.w,  a3.x, a3.y, a3.z, a3.w };

    float o00 = 0.f, o01 = 0.f, o02 = 0.f, o03 = 0.f;
    #pragma unroll
    for (int k = 0; k < 13; k++) {
        float ck = comp[k];
        o00 = fmaf(ck, xs0[k + 0], o00);
        o01 = fmaf(ck, xs0[k + 1], o01);
        o02 = fmaf(ck, xs0[k + 2], o02);
        o03 = fmaf(ck, xs0[k + 3], o03);
    }
    float4 r0; r0.x = o00; r0.y = o01; r0.z = o02; r0.w = o03;
    reinterpret_cast<float4*>(orow)[v0] = r0;

    if (p1) {
        float xs1[16] = { b0.x, b0.y, b0.z, b0.w,  b1.x, b1.y, b1.z, b1.w,
                          b2.x, b2.y, b2.z, b2.w,  b3.x, b3.y, b3.z, b3.w };
        float o10 = 0.f, o11 = 0.f, o12 = 0.f, o13 = 0.f;
        #pragma unroll
        for (int k = 0; k < 13; k++) {
            float ck = comp[k];
            o10 = fmaf(ck, xs1[k + 0], o10);
            o11 = fmaf(ck, xs1[k + 1], o11);
            o12 = fmaf(ck, xs1[k + 2], o12);
            o13 = fmaf(ck, xs1[k + 3], o13);
        }
        float4 r1; r1.x = o10; r1.y = o11; r1.z = o12; r1.w = o13;
        reinterpret_cast<float4*>(orow)[v1] = r1;
    }
}

extern "C" void kernel_launch(void* const* d_in, const int* in_sizes, int n_in,
                              void* d_out, int out_size) {
    const float* x     = (const float*)d_in[0];
    const float* fd    = (const float*)d_in[1];
    const float* gauss = (const float*)d_in[2];
    float* out = (float*)d_out;

    compute_comp_kernel<<<1, 32>>>(fd, gauss);

    dim3 grid(BPR, ROWS);
    stencil13_kernel<<<grid, TPB>>>(x, out);
}

// round 4
// speedup vs baseline: 1.2535x; 1.0773x over previous
#include <cuda_runtime.h>

// x is [8, 4, 1048576] fp32.
constexpr int T_IN  = 1048576;
constexpr int T_OUT = T_IN - 12;        // 1048564
constexpr int NVEC  = T_OUT / 4;        // 262141 float4 outputs per row
constexpr int ROWS  = 8 * 4;            // 32 rows
constexpr int TPB   = 256;
constexpr int KINT  = 4;                // interleaved float4 vectors per thread
constexpr int VPB   = TPB * KINT;       // 1024 output vectors per block
constexpr int BPR   = (NVEC + VPB - 1) / VPB;   // 256 blocks per row

__global__ __launch_bounds__(TPB)
void stencil13_kernel(const float* __restrict__ x,
                      const float* __restrict__ fd,
                      const float* __restrict__ gauss,
                      float* __restrict__ out) {
    // Composite 13-tap kernel (fd ⊛ gauss), computed once per block.
    __shared__ float s_comp[13];
    if (threadIdx.x < 13) {
        float s = 0.0f;
        #pragma unroll
        for (int i = 0; i < 5; i++) {
            int j = (int)threadIdx.x - i;
            if (j >= 0 && j < 9) s += __ldg(fd + i) * __ldg(gauss + j);
        }
        s_comp[threadIdx.x] = s;
    }
    __syncthreads();

    const int row = blockIdx.y;
    const float* xrow = x + (long)row * T_IN;
    float*       orow = out + (long)row * T_OUT;

    const int v0 = blockIdx.x * VPB + threadIdx.x;

    // Front-batch all loads: up to 16 independent LDG.128, streaming hint.
    float4 va[KINT][4];
    bool   p[KINT];
    #pragma unroll
    for (int j = 0; j < KINT; j++) {
        const int vj = v0 + j * TPB;
        p[j] = (vj < NVEC);
        if (p[j]) {
            const float4* xin = reinterpret_cast<const float4*>(xrow + 4L * vj);
            va[j][0] = __ldcs(xin + 0);
            va[j][1] = __ldcs(xin + 1);
            va[j][2] = __ldcs(xin + 2);
            va[j][3] = __ldcs(xin + 3);
        }
    }

    float comp[13];
    #pragma unroll
    for (int k = 0; k < 13; k++) comp[k] = s_comp[k];

    #pragma unroll
    for (int j = 0; j < KINT; j++) {
        if (p[j]) {
            float xs[16] = { va[j][0].x, va[j][0].y, va[j][0].z, va[j][0].w,
                             va[j][1].x, va[j][1].y, va[j][1].z, va[j][1].w,
                             va[j][2].x, va[j][2].y, va[j][2].z, va[j][2].w,
                             va[j][3].x, va[j][3].y, va[j][3].z, va[j][3].w };
            float o0 = 0.f, o1 = 0.f, o2 = 0.f, o3 = 0.f;
            #pragma unroll
            for (int k = 0; k < 13; k++) {
                const float ck = comp[k];
                o0 = fmaf(ck, xs[k + 0], o0);
                o1 = fmaf(ck, xs[k + 1], o1);
                o2 = fmaf(ck, xs[k + 2], o2);
                o3 = fmaf(ck, xs[k + 3], o3);
            }
            float4 r; r.x = o0; r.y = o1; r.z = o2; r.w = o3;
            __stcs(reinterpret_cast<float4*>(orow) + (v0 + j * TPB), r);
        }
    }
}

extern "C" void kernel_launch(void* const* d_in, const int* in_sizes, int n_in,
                              void* d_out, int out_size) {
    const float* x     = (const float*)d_in[0];  // [8,4,1048576] f32
    const float* fd    = (const float*)d_in[1];  // [5]  f32
    const float* gauss = (const float*)d_in[2];  // [9]  f32
    float* out = (float*)d_out;                  // [8,4,1048564] f32

    dim3 grid(BPR, ROWS);
    stencil13_kernel<<<grid, TPB>>>(x, fd, gauss, out);
}